// round 1
// baseline (speedup 1.0000x reference)
#include <cuda_runtime.h>
#include <math.h>
#include <stdint.h>

// Problem constants
#define HNUM 256
#define WNUM 256
#define MC   128
#define NSQ  32
#define RR   (NSQ * NSQ)     // 1024
#define TT   512
#define BIN_LEN 0.02f
#define EPS_NORM 1e-12f

// Output layout (all float32, concatenated flattened tuple):
//   origins_out  (MC,RR,3)
//   directions   (MC,RR,3)
//   t            (MC,RR,TT)
//   xys          (MC,RR,2)
#define OFF_ORI 0
#define OFF_DIR (MC * RR * 3)                 // 393216
#define OFF_T   (2 * MC * RR * 3)             // 786432
#define OFF_XYS (2 * MC * RR * 3 + MC * RR * TT)  // 67895296

// Per-m scratch (device globals; no allocation allowed)
__device__ float g_orig[MC][3];
__device__ float g_lvec[MC][3];
__device__ float g_l[MC];
__device__ float g_d1d4[MC];
__device__ float g_eff[MC];
__device__ float g_y[MC];
__device__ float g_x[MC];
__device__ int   g_flag[MC];

__device__ __forceinline__ float norm3(float a, float b, float c) {
    return sqrtf(__fadd_rn(__fadd_rn(__fmul_rn(a, a), __fmul_rn(b, b)), __fmul_rn(c, c)));
}

// ---------------------------------------------------------------------------
// Kernel 1: per-m precompute (1 block, MC threads)
// ---------------------------------------------------------------------------
__global__ void precompute_kernel(const float* __restrict__ laser_pos,
                                  const float* __restrict__ camera_pos,
                                  const float* __restrict__ laser_origin,
                                  const float* __restrict__ camera_origin,
                                  const int*   __restrict__ idx_raw) {
    __shared__ int is64;
    int m = threadIdx.x;
    if (m == 0) {
        // Sniff idx_perm dtype: if int64 little-endian, every odd int32 slot
        // (high word) among the first 64 elements is 0. If int32, those slots
        // are distinct permutation values (at most one zero).
        int zeros = 0;
        #pragma unroll 1
        for (int k = 1; k < 128; k += 2) zeros += (idx_raw[k] == 0);
        is64 = (zeros >= 2) ? 1 : 0;
    }
    __syncthreads();
    if (m >= MC) return;

    long long idx;
    if (is64) idx = ((const long long*)idx_raw)[m];
    else      idx = (long long)idx_raw[m];

    int y = (int)(idx / WNUM);
    int x = (int)(idx % WNUM);
    if (m == 0) { y = HNUM / 2; x = WNUM / 2; }

    int base = (y * WNUM + x) * 3;
    float lpx = laser_pos[base + 0], lpy = laser_pos[base + 1], lpz = laser_pos[base + 2];
    float cpx = camera_pos[base + 0], cpy = camera_pos[base + 1], cpz = camera_pos[base + 2];
    float lox = laser_origin[0], loy = laser_origin[1], loz = laser_origin[2];
    float cox = camera_origin[0], coy = camera_origin[1], coz = camera_origin[2];

    float d1 = norm3(__fsub_rn(lpx, lox), __fsub_rn(lpy, loy), __fsub_rn(lpz, loz));
    float d4 = norm3(__fsub_rn(cpx, cox), __fsub_rn(cpy, coy), __fsub_rn(cpz, coz));
    float d1d4 = __fadd_rn(d1, d4);

    float vx = __fsub_rn(lpx, cpx);
    float vy = __fsub_rn(lpy, cpy);
    float vz = __fsub_rn(lpz, cpz);
    float l = norm3(vx, vy, vz);
    float inv = __fdiv_rn(1.0f, fmaxf(l, EPS_NORM));

    // idx_offset = ceil((||lp-cp|| - d_offset)/BIN_LEN) ; eff = mod(int32, T)
    float off_f = ceilf(__fdiv_rn(__fsub_rn(l, d1d4), BIN_LEN));
    int offset = (int)off_f;
    int eff = offset % TT;
    if (eff < 0) eff += TT;

    g_orig[m][0] = cpx; g_orig[m][1] = cpy; g_orig[m][2] = cpz;
    g_lvec[m][0] = __fmul_rn(vx, inv);
    g_lvec[m][1] = __fmul_rn(vy, inv);
    g_lvec[m][2] = __fmul_rn(vz, inv);
    g_l[m] = l;
    g_d1d4[m] = d1d4;
    g_eff[m] = (float)eff;
    g_y[m] = (float)y;
    g_x[m] = (float)x;
    g_flag[m] = 0;
}

// ---------------------------------------------------------------------------
// Kernel 2: main write. One block per (r,m) row; 128 threads, each writes a
// float4 of t (512 t-bins). Also writes origins/directions/xys from 8 lanes.
// ---------------------------------------------------------------------------
__global__ void __launch_bounds__(128, 16)
main_kernel(const float* __restrict__ dirs, float* __restrict__ out) {
    const int r = blockIdx.x;
    const int m = blockIdx.y;
    const int tid = threadIdx.x;

    const float lvx = g_lvec[m][0], lvy = g_lvec[m][1], lvz = g_lvec[m][2];
    const float d0 = dirs[r * 3 + 0], d1 = dirs[r * 3 + 1], d2 = dirs[r * 3 + 2];

    // dx = dot(direction_r, lvec_m); dy = sqrt(1 - dx^2) (NaN if dx^2 > 1)
    float dx = __fadd_rn(__fadd_rn(__fmul_rn(d0, lvx), __fmul_rn(d1, lvy)), __fmul_rn(d2, lvz));
    float dx2 = __fmul_rn(dx, dx);
    float dy = sqrtf(__fsub_rn(1.0f, dx2));
    float dy2 = __fmul_rn(dy, dy);

    const float l = g_l[m];
    const float l2 = __fmul_rn(l, l);
    const float dxl = __fmul_rn(dx, l);
    const float eff = g_eff[m];

    const int t0 = tid * 4;
    float4 v4;
    bool anynan = false;

    #pragma unroll
    for (int j = 0; j < 4; j++) {
        float tf   = (float)(t0 + j);
        float tau  = __fmul_rn(BIN_LEN, fmaxf(tf, eff));
        float tau2 = __fmul_rn(tau, tau);
        float diff = __fsub_rn(tau2, l2);
        float num  = __fmul_rn(__fadd_rn(dxl, tau), diff);
        float den  = __fmul_rn(2.0f, __fadd_rn(__fmul_rn(dx2, diff), __fmul_rn(dy2, tau2)));
        float v    = __fdiv_rn(num, den);
        anynan |= (v != v);
        ((float*)&v4)[j] = v;
    }

    size_t row = (size_t)m * RR + r;
    float4* trow = (float4*)(out + OFF_T + row * TT);
    trow[tid] = v4;

    // Per-m NaN flag: ballot within warp, one atomic per warp only if needed.
    unsigned ball = __ballot_sync(0xffffffffu, anynan);
    if (ball != 0u && (tid & 31) == 0) atomicOr(&g_flag[m], 1);

    // Small outputs
    if (tid < 8) {
        if (tid < 3)      out[OFF_ORI + row * 3 + tid]       = g_orig[m][tid];
        else if (tid < 6) out[OFF_DIR + row * 3 + (tid - 3)] = dirs[r * 3 + (tid - 3)];
        else if (tid == 6) out[OFF_XYS + row * 2 + 0] = g_y[m];
        else               out[OFF_XYS + row * 2 + 1] = g_x[m];
    }
}

// ---------------------------------------------------------------------------
// Kernel 3: fixup. Rows of m with a NaN anywhere get t_conf broadcast over r.
// Blocks for unflagged m exit immediately (expected common case: 0 flagged).
// ---------------------------------------------------------------------------
__global__ void __launch_bounds__(128, 16)
fixup_kernel(float* __restrict__ out) {
    const int m = blockIdx.y;
    if (!g_flag[m]) return;
    const int r = blockIdx.x;
    const float d1d4 = g_d1d4[m];
    const int t0 = threadIdx.x * 4;

    float4 v4;
    #pragma unroll
    for (int j = 0; j < 4; j++) {
        float tau0 = __fmul_rn((float)(t0 + j), BIN_LEN);
        float d = __fsub_rn(tau0, d1d4);
        if (d <= 0.0f) d = 1e-6f;
        ((float*)&v4)[j] = __fmul_rn(d, 0.5f);
    }
    size_t row = (size_t)m * RR + r;
    ((float4*)(out + OFF_T + row * TT))[threadIdx.x] = v4;
}

// ---------------------------------------------------------------------------
extern "C" void kernel_launch(void* const* d_in, const int* in_sizes, int n_in,
                              void* d_out, int out_size) {
    const float* laser_pos     = (const float*)d_in[0];
    const float* camera_pos    = (const float*)d_in[1];
    const float* laser_origin  = (const float*)d_in[2];
    const float* camera_origin = (const float*)d_in[3];
    const float* directions    = (const float*)d_in[4];
    const int*   idx_raw       = (const int*)d_in[5];
    float* out = (float*)d_out;

    precompute_kernel<<<1, 128>>>(laser_pos, camera_pos, laser_origin,
                                  camera_origin, idx_raw);

    dim3 grid(RR, MC);
    main_kernel<<<grid, 128>>>(directions, out);
    fixup_kernel<<<grid, 128>>>(out);
}

// round 2
// speedup vs baseline: 3.1153x; 3.1153x over previous
#include <cuda_runtime.h>
#include <math.h>
#include <stdint.h>

// Problem constants
#define HNUM 256
#define WNUM 256
#define MC   128
#define NSQ  32
#define RR   (NSQ * NSQ)     // 1024
#define TT   512
#define BIN_LEN 0.02f
#define EPS_NORM 1e-12f

// Output layout (all float32, concatenated flattened tuple):
//   origins_out  (MC,RR,3) | directions (MC,RR,3) | t (MC,RR,TT) | xys (MC,RR,2)
#define OFF_ORI 0
#define OFF_DIR (MC * RR * 3)                          // 393216
#define OFF_T   (2 * MC * RR * 3)                      // 786432
#define OFF_XYS (2 * MC * RR * 3 + MC * RR * TT)       // 67895296

// Per-m scratch (device globals; no allocation allowed)
__device__ float g_orig[MC][3];
__device__ float g_lvec[MC][3];
__device__ float g_l[MC];
__device__ float g_d1d4[MC];
__device__ float g_eff[MC];
__device__ float g_y[MC];
__device__ float g_x[MC];
__device__ int   g_flag[MC];

__device__ __forceinline__ float norm3(float a, float b, float c) {
    return sqrtf(__fadd_rn(__fadd_rn(__fmul_rn(a, a), __fmul_rn(b, b)), __fmul_rn(c, c)));
}

// ---------------------------------------------------------------------------
// Kernel 1: per-m precompute (1 block, MC threads). Warp-ballot dtype sniff.
// ---------------------------------------------------------------------------
__global__ void precompute_kernel(const float* __restrict__ laser_pos,
                                  const float* __restrict__ camera_pos,
                                  const float* __restrict__ laser_origin,
                                  const float* __restrict__ camera_origin,
                                  const int*   __restrict__ idx_raw) {
    int m = threadIdx.x;
    if (m >= MC) return;
    int lane = m & 31;

    // Sniff idx_perm dtype: if int64 (little-endian), the high int32 word of
    // each of the first 32 elements is 0. If int32, those odd slots hold
    // distinct permutation values (at most one zero). Every warp does the
    // same ballot so no cross-warp sync is needed.
    int hz = (idx_raw[2 * lane + 1] == 0);
    unsigned ball = __ballot_sync(0xffffffffu, hz);
    int is64 = (__popc(ball) >= 2);

    long long idx;
    if (is64) idx = ((const long long*)idx_raw)[m];
    else      idx = (long long)idx_raw[m];

    int y = (int)(idx / WNUM);
    int x = (int)(idx % WNUM);
    if (m == 0) { y = HNUM / 2; x = WNUM / 2; }

    int base = (y * WNUM + x) * 3;
    float lpx = laser_pos[base + 0], lpy = laser_pos[base + 1], lpz = laser_pos[base + 2];
    float cpx = camera_pos[base + 0], cpy = camera_pos[base + 1], cpz = camera_pos[base + 2];
    float lox = laser_origin[0], loy = laser_origin[1], loz = laser_origin[2];
    float cox = camera_origin[0], coy = camera_origin[1], coz = camera_origin[2];

    float d1 = norm3(__fsub_rn(lpx, lox), __fsub_rn(lpy, loy), __fsub_rn(lpz, loz));
    float d4 = norm3(__fsub_rn(cpx, cox), __fsub_rn(cpy, coy), __fsub_rn(cpz, coz));
    float d1d4 = __fadd_rn(d1, d4);

    float vx = __fsub_rn(lpx, cpx);
    float vy = __fsub_rn(lpy, cpy);
    float vz = __fsub_rn(lpz, cpz);
    float l = norm3(vx, vy, vz);
    float inv = __fdiv_rn(1.0f, fmaxf(l, EPS_NORM));

    float off_f = ceilf(__fdiv_rn(__fsub_rn(l, d1d4), BIN_LEN));
    int offset = (int)off_f;
    int eff = offset % TT;
    if (eff < 0) eff += TT;

    g_orig[m][0] = cpx; g_orig[m][1] = cpy; g_orig[m][2] = cpz;
    g_lvec[m][0] = __fmul_rn(vx, inv);
    g_lvec[m][1] = __fmul_rn(vy, inv);
    g_lvec[m][2] = __fmul_rn(vz, inv);
    g_l[m] = l;
    g_d1d4[m] = d1d4;
    g_eff[m] = (float)eff;
    g_y[m] = (float)y;
    g_x[m] = (float)x;
    g_flag[m] = 0;
}

// ---------------------------------------------------------------------------
// Kernel 2: main t write. One WARP per (m,r) row; 8 rows per 256-thread block.
// Each thread computes 16 t-bins as 4 float4 streaming stores (coalesced).
// den/num/dx/dy keep the exact reference rounding (pole elements dominate
// the output norm); only the final division is relaxed to __fdividef.
// ---------------------------------------------------------------------------
__global__ void __launch_bounds__(256, 8)
main_kernel(const float* __restrict__ dirs, float* __restrict__ out) {
    const int m = blockIdx.y;
    const int warp = threadIdx.x >> 5;
    const int lane = threadIdx.x & 31;
    const int r = blockIdx.x * 8 + warp;

    const float lvx = g_lvec[m][0], lvy = g_lvec[m][1], lvz = g_lvec[m][2];
    const float l   = g_l[m];
    const float eff = g_eff[m];

    const float d0 = __ldg(&dirs[r * 3 + 0]);
    const float d1 = __ldg(&dirs[r * 3 + 1]);
    const float d2 = __ldg(&dirs[r * 3 + 2]);

    // dx = dot(direction_r, lvec_m); dy = sqrt(1 - dx^2) (NaN if dx^2 > 1)
    float dx  = __fadd_rn(__fadd_rn(__fmul_rn(d0, lvx), __fmul_rn(d1, lvy)), __fmul_rn(d2, lvz));
    float dx2 = __fmul_rn(dx, dx);
    float dy  = sqrtf(__fsub_rn(1.0f, dx2));
    float dy2 = __fmul_rn(dy, dy);
    float l2  = __fmul_rn(l, l);
    float dxl = __fmul_rn(dx, l);

    float4* trow = (float4*)(out + OFF_T + ((size_t)m * RR + r) * TT);
    bool anynan = false;

    #pragma unroll
    for (int j = 0; j < 4; j++) {
        const int i4 = j * 32 + lane;         // float4 index in row
        float4 v4;
        #pragma unroll
        for (int k = 0; k < 4; k++) {
            float tf   = (float)(i4 * 4 + k);
            float tau  = __fmul_rn(BIN_LEN, fmaxf(tf, eff));
            float tau2 = __fmul_rn(tau, tau);
            float diff = __fsub_rn(tau2, l2);
            float num  = __fmul_rn(__fadd_rn(dxl, tau), diff);
            float den  = __fmul_rn(2.0f,
                           __fadd_rn(__fmul_rn(dx2, diff), __fmul_rn(dy2, tau2)));
            float v    = __fdividef(num, den);
            anynan |= (v != v);
            ((float*)&v4)[k] = v;
        }
        __stcs(&trow[i4], v4);
    }

    unsigned ball = __ballot_sync(0xffffffffu, anynan);
    if (ball != 0u && lane == 0) atomicOr(&g_flag[m], 1);
}

// ---------------------------------------------------------------------------
// Kernel 3: small outputs (origins/directions/xys), fully coalesced.
// ---------------------------------------------------------------------------
__global__ void smallout_kernel(const float* __restrict__ dirs,
                                float* __restrict__ out) {
    const int NORI = MC * RR * 3;   // 393216
    const int NXY  = MC * RR * 2;   // 262144
    const int total = 2 * NORI + NXY;
    int idx = blockIdx.x * blockDim.x + threadIdx.x;
    for (; idx < total; idx += gridDim.x * blockDim.x) {
        float v; int o;
        if (idx < NORI) {
            int m = idx / (RR * 3);
            v = g_orig[m][idx % 3];
            o = OFF_ORI + idx;
        } else if (idx < 2 * NORI) {
            int e = idx - NORI;
            v = dirs[e % (RR * 3)];
            o = OFF_DIR + e;
        } else {
            int e = idx - 2 * NORI;
            int m = e >> 11;                 // / (RR*2)
            v = (e & 1) ? g_x[m] : g_y[m];
            o = OFF_XYS + e;
        }
        out[o] = v;
    }
}

// ---------------------------------------------------------------------------
// Kernel 4: fixup. One block per m; early-exits unless flagged (rare case).
// ---------------------------------------------------------------------------
__global__ void __launch_bounds__(128)
fixup_kernel(float* __restrict__ out) {
    const int m = blockIdx.x;
    if (!g_flag[m]) return;
    const float d1d4 = g_d1d4[m];
    const int t0 = threadIdx.x * 4;

    float4 v4;
    #pragma unroll
    for (int j = 0; j < 4; j++) {
        float tau0 = __fmul_rn((float)(t0 + j), BIN_LEN);
        float d = __fsub_rn(tau0, d1d4);
        if (d <= 0.0f) d = 1e-6f;
        ((float*)&v4)[j] = __fmul_rn(d, 0.5f);
    }
    for (int r = 0; r < RR; r++) {
        ((float4*)(out + OFF_T + ((size_t)m * RR + r) * TT))[threadIdx.x] = v4;
    }
}

// ---------------------------------------------------------------------------
extern "C" void kernel_launch(void* const* d_in, const int* in_sizes, int n_in,
                              void* d_out, int out_size) {
    const float* laser_pos     = (const float*)d_in[0];
    const float* camera_pos    = (const float*)d_in[1];
    const float* laser_origin  = (const float*)d_in[2];
    const float* camera_origin = (const float*)d_in[3];
    const float* directions    = (const float*)d_in[4];
    const int*   idx_raw       = (const int*)d_in[5];
    float* out = (float*)d_out;

    precompute_kernel<<<1, 128>>>(laser_pos, camera_pos, laser_origin,
                                  camera_origin, idx_raw);

    dim3 grid(RR / 8, MC);
    main_kernel<<<grid, 256>>>(directions, out);
    smallout_kernel<<<1024, 256>>>(directions, out);
    fixup_kernel<<<MC, 128>>>(out);
}

// round 3
// speedup vs baseline: 3.8656x; 1.2408x over previous
#include <cuda_runtime.h>
#include <math.h>
#include <stdint.h>

// Problem constants
#define HNUM 256
#define WNUM 256
#define MC   128
#define NSQ  32
#define RR   (NSQ * NSQ)     // 1024
#define TT   512
#define BIN_LEN 0.02f
#define EPS_NORM 1e-12f

// Output layout (all float32, concatenated flattened tuple):
//   origins_out  (MC,RR,3) | directions (MC,RR,3) | t (MC,RR,TT) | xys (MC,RR,2)
#define OFF_ORI 0
#define OFF_DIR (MC * RR * 3)                          // 393216
#define OFF_T   (2 * MC * RR * 3)                      // 786432
#define OFF_XYS (2 * MC * RR * 3 + MC * RR * TT)       // 67895296

#define NTHREADS 1024

__device__ __forceinline__ float norm3(float a, float b, float c) {
    return sqrtf(__fadd_rn(__fadd_rn(__fmul_rn(a, a), __fmul_rn(b, b)), __fmul_rn(c, c)));
}

// ---------------------------------------------------------------------------
// Single fused kernel. One block per m (grid=128, 1024 threads).
//  - warp 0 computes per-m scalars into shared (incl. idx dtype sniff)
//  - coalesced loops write origins/directions/xys slices for this m
//  - 32 warps x 32 rows write t (each lane: 16 bins as 4 float4 stcs stores)
//  - block-local NaN flag -> in-block fixup rewrite with t_conf (rare path)
// Arithmetic for dx/dy/num/den is bit-identical to the reference ordering;
// only the final division is __fdividef (validated: rel_err ~6e-8).
// ---------------------------------------------------------------------------
__global__ void __launch_bounds__(NTHREADS, 1)
fused_kernel(const float* __restrict__ laser_pos,
             const float* __restrict__ camera_pos,
             const float* __restrict__ laser_origin,
             const float* __restrict__ camera_origin,
             const float* __restrict__ dirs,
             const int*   __restrict__ idx_raw,
             float* __restrict__ out) {
    __shared__ float s_orig[3], s_lvec[3];
    __shared__ float s_l, s_eff, s_d1d4, s_y, s_x;
    __shared__ int   s_flag;

    const int m   = blockIdx.x;
    const int tid = threadIdx.x;

    // ---- per-m scalar setup (warp 0) ----
    if (tid < 32) {
        // dtype sniff: int64 little-endian => high words of first 32 elems are 0
        int hz = (idx_raw[2 * tid + 1] == 0);
        unsigned ball = __ballot_sync(0xffffffffu, hz);
        int is64 = (__popc(ball) >= 2);

        if (tid == 0) {
            long long idx = is64 ? ((const long long*)idx_raw)[m]
                                 : (long long)idx_raw[m];
            int y = (int)(idx / WNUM);
            int x = (int)(idx % WNUM);
            if (m == 0) { y = HNUM / 2; x = WNUM / 2; }

            int base = (y * WNUM + x) * 3;
            float lpx = laser_pos[base + 0], lpy = laser_pos[base + 1], lpz = laser_pos[base + 2];
            float cpx = camera_pos[base + 0], cpy = camera_pos[base + 1], cpz = camera_pos[base + 2];

            float d1 = norm3(__fsub_rn(lpx, laser_origin[0]),
                             __fsub_rn(lpy, laser_origin[1]),
                             __fsub_rn(lpz, laser_origin[2]));
            float d4 = norm3(__fsub_rn(cpx, camera_origin[0]),
                             __fsub_rn(cpy, camera_origin[1]),
                             __fsub_rn(cpz, camera_origin[2]));
            float d1d4 = __fadd_rn(d1, d4);

            float vx = __fsub_rn(lpx, cpx);
            float vy = __fsub_rn(lpy, cpy);
            float vz = __fsub_rn(lpz, cpz);
            float l  = norm3(vx, vy, vz);
            float inv = __fdiv_rn(1.0f, fmaxf(l, EPS_NORM));

            float off_f = ceilf(__fdiv_rn(__fsub_rn(l, d1d4), BIN_LEN));
            int offset = (int)off_f;
            int eff = offset % TT;
            if (eff < 0) eff += TT;

            s_orig[0] = cpx; s_orig[1] = cpy; s_orig[2] = cpz;
            s_lvec[0] = __fmul_rn(vx, inv);
            s_lvec[1] = __fmul_rn(vy, inv);
            s_lvec[2] = __fmul_rn(vz, inv);
            s_l = l; s_d1d4 = d1d4; s_eff = (float)eff;
            s_y = (float)y; s_x = (float)x;
            s_flag = 0;
        }
    }
    __syncthreads();

    const float lvx = s_lvec[0], lvy = s_lvec[1], lvz = s_lvec[2];
    const float ox  = s_orig[0], oy  = s_orig[1], oz  = s_orig[2];
    const float l   = s_l;
    const float eff = s_eff;
    const float yv  = s_y, xv = s_x;
    const float l2  = __fmul_rn(l, l);

    // ---- small outputs for this m (coalesced) ----
    {
        float* po = out + OFF_ORI + (size_t)m * (RR * 3);
        float* pd = out + OFF_DIR + (size_t)m * (RR * 3);
        #pragma unroll
        for (int i = tid; i < RR * 3; i += NTHREADS) {
            int c = i % 3;
            po[i] = (c == 0) ? ox : (c == 1) ? oy : oz;
            pd[i] = __ldg(&dirs[i]);
        }
        float* pxy = out + OFF_XYS + (size_t)m * (RR * 2);
        #pragma unroll
        for (int i = tid; i < RR * 2; i += NTHREADS) {
            pxy[i] = (i & 1) ? xv : yv;
        }
    }

    // ---- t tensor: warp-per-row ----
    const int warp = tid >> 5;
    const int lane = tid & 31;
    bool anynan = false;

    #pragma unroll 1
    for (int rw = 0; rw < RR / 32; rw++) {
        const int r = rw * 32 + warp;

        const float d0 = __ldg(&dirs[r * 3 + 0]);
        const float d1 = __ldg(&dirs[r * 3 + 1]);
        const float d2 = __ldg(&dirs[r * 3 + 2]);

        float dx  = __fadd_rn(__fadd_rn(__fmul_rn(d0, lvx), __fmul_rn(d1, lvy)),
                              __fmul_rn(d2, lvz));
        float dx2 = __fmul_rn(dx, dx);
        float dy  = sqrtf(__fsub_rn(1.0f, dx2));
        float dy2 = __fmul_rn(dy, dy);
        float dxl = __fmul_rn(dx, l);

        float4* trow = (float4*)(out + OFF_T + ((size_t)m * RR + r) * TT);

        #pragma unroll
        for (int j = 0; j < 4; j++) {
            const int i4 = j * 32 + lane;
            float4 v4;
            #pragma unroll
            for (int k = 0; k < 4; k++) {
                float tf   = (float)(i4 * 4 + k);
                float tau  = __fmul_rn(BIN_LEN, fmaxf(tf, eff));
                float tau2 = __fmul_rn(tau, tau);
                float diff = __fsub_rn(tau2, l2);
                float num  = __fmul_rn(__fadd_rn(dxl, tau), diff);
                float den  = __fmul_rn(2.0f,
                               __fadd_rn(__fmul_rn(dx2, diff), __fmul_rn(dy2, tau2)));
                float v    = __fdividef(num, den);
                anynan |= (v != v);
                ((float*)&v4)[k] = v;
            }
            __stcs(&trow[i4], v4);
        }
    }

    // ---- NaN flag reduce + in-block fixup (rare path) ----
    unsigned ball = __ballot_sync(0xffffffffu, anynan);
    if (ball != 0u && lane == 0) atomicOr(&s_flag, 1);
    __syncthreads();

    if (s_flag) {
        const float d1d4 = s_d1d4;
        // Precompute this lane's t_conf float4s (depend only on t index).
        float4 c4[4];
        #pragma unroll
        for (int j = 0; j < 4; j++) {
            const int i4 = j * 32 + lane;
            #pragma unroll
            for (int k = 0; k < 4; k++) {
                float tau0 = __fmul_rn((float)(i4 * 4 + k), BIN_LEN);
                float d = __fsub_rn(tau0, d1d4);
                if (d <= 0.0f) d = 1e-6f;
                ((float*)&c4[j])[k] = __fmul_rn(d, 0.5f);
            }
        }
        #pragma unroll 1
        for (int rw = 0; rw < RR / 32; rw++) {
            const int r = rw * 32 + warp;
            float4* trow = (float4*)(out + OFF_T + ((size_t)m * RR + r) * TT);
            #pragma unroll
            for (int j = 0; j < 4; j++) {
                trow[j * 32 + lane] = c4[j];
            }
        }
    }
}

// ---------------------------------------------------------------------------
extern "C" void kernel_launch(void* const* d_in, const int* in_sizes, int n_in,
                              void* d_out, int out_size) {
    const float* laser_pos     = (const float*)d_in[0];
    const float* camera_pos    = (const float*)d_in[1];
    const float* laser_origin  = (const float*)d_in[2];
    const float* camera_origin = (const float*)d_in[3];
    const float* directions    = (const float*)d_in[4];
    const int*   idx_raw       = (const int*)d_in[5];
    float* out = (float*)d_out;

    fused_kernel<<<MC, NTHREADS>>>(laser_pos, camera_pos, laser_origin,
                                   camera_origin, directions, idx_raw, out);
}